// round 17
// baseline (speedup 1.0000x reference)
#include <cuda_runtime.h>
#include <math.h>

#define BB 8
#define CC 256
#define HH 56
#define WW 56
#define HW (HH*WW)          // 3136
#define KK 3
#define TAPS 9
#define MID 51
#define CKK (CC*TAPS)       // 2304
#define GAIN_OVER_K 0.4714045207910317f   // sqrt(2)/3

#define NSF 98               // sf blocks per batch
#define NCF 16               // pool+cf blocks per batch
#define NDF 224              // ddf blocks per batch (7 row-tiles x 32 cgroups)
#define SF_END  (BB*NSF)     // 784
#define CF_END  (SF_END + BB*NCF)   // 912

__device__ __align__(16) float g_pooled[BB * CC];
__device__ __align__(16) float g_sf[BB * TAPS * HW];
__device__ __align__(16) float g_cf[BB * CKK];
__device__ unsigned g_pcnt[BB]  = {0};
__device__ unsigned g_sfcnt[BB] = {0};
__device__ unsigned g_cfcnt[BB] = {0};
__device__ unsigned g_ddftkt[BB] = {0};

typedef unsigned long long ull;

__device__ __forceinline__ ull pack2(float x, float y) {
    ull r; asm("mov.b64 %0, {%1, %2};" : "=l"(r) : "f"(x), "f"(y)); return r;
}
__device__ __forceinline__ void unpack2(ull v, float& x, float& y) {
    asm("mov.b64 {%0, %1}, %2;" : "=f"(x), "=f"(y) : "l"(v));
}
__device__ __forceinline__ ull mul2(ull a, ull b) {
    ull d; asm("mul.rn.f32x2 %0, %1, %2;" : "=l"(d) : "l"(a), "l"(b)); return d;
}
__device__ __forceinline__ ull add2(ull a, ull b) {
    ull d; asm("add.rn.f32x2 %0, %1, %2;" : "=l"(d) : "l"(a), "l"(b)); return d;
}
__device__ __forceinline__ ull fma2(ull a, ull b, ull c) {
    ull d; asm("fma.rn.f32x2 %0, %1, %2, %3;" : "=l"(d) : "l"(a), "l"(b), "l"(c)); return d;
}
__device__ __forceinline__ unsigned smem_u32(const void* p) {
    unsigned a;
    asm("{ .reg .u64 t; cvta.to.shared.u64 t, %1; cvt.u32.u64 %0, t; }"
        : "=r"(a) : "l"(p));
    return a;
}

#define K3_CG 8
#define HSTR 56
#define HSZ  (10 * HSTR)     // 560

// smem union: sf 21504 B (max) | cf 16544 B | ddf ~18.6 KB
#define SMEM_BYTES 21504

__global__ void __launch_bounds__(256, 7) mega(
    const float* __restrict__ x,
    const float* __restrict__ ws,
    const float* __restrict__ bs,
    const float* __restrict__ w1, const float* __restrict__ b1,
    const float* __restrict__ w2, const float* __restrict__ b2,
    const float* __restrict__ fn_std,
    float* __restrict__ out)
{
    __shared__ __align__(16) char sm[SMEM_BYTES];
    __shared__ __align__(8)  ull mbar_st;
    __shared__ unsigned u0_s, u1_s;

    const int bid  = blockIdx.x;
    const int tid  = threadIdx.x;
    const int lane = tid & 31;
    const int w    = tid >> 5;

    if (bid < SF_END) {
        // ===================== sf block =====================
        const int b  = bid / NSF;
        const int bx = bid % NSF;
        float* ws_s = (float*)sm;                 // 12288 B
        float* red  = (float*)(sm + 12288);       // 9216 B

#pragma unroll
        for (int i = tid; i < TAPS * CC; i += 256) {
            int n = i >> 8, c = i & 255;
            ws_s[c * 12 + n] = ws[i];
        }
        __syncthreads();

        const int pix = bx * 32 + lane;
        const float* xb = x + ((size_t)b * CC + w * 32) * HW + pix;

        float acc[TAPS];
#pragma unroll
        for (int n = 0; n < TAPS; n++) acc[n] = 0.f;

#pragma unroll 8
        for (int cc = 0; cc < 32; cc++) {
            float xv = __ldg(xb + (size_t)cc * HW);
            const float* wr = ws_s + (w * 32 + cc) * 12;
            float4 wa = *(const float4*)(wr);
            float4 wb = *(const float4*)(wr + 4);
            float  w8 = wr[8];
            acc[0] = fmaf(xv, wa.x, acc[0]);
            acc[1] = fmaf(xv, wa.y, acc[1]);
            acc[2] = fmaf(xv, wa.z, acc[2]);
            acc[3] = fmaf(xv, wa.w, acc[3]);
            acc[4] = fmaf(xv, wb.x, acc[4]);
            acc[5] = fmaf(xv, wb.y, acc[5]);
            acc[6] = fmaf(xv, wb.z, acc[6]);
            acc[7] = fmaf(xv, wb.w, acc[7]);
            acc[8] = fmaf(xv, w8,   acc[8]);
        }

#pragma unroll
        for (int n = 0; n < TAPS; n++)
            red[(w * TAPS + n) * 32 + lane] = acc[n];
        __syncthreads();

        if (tid < 32) {
            float a[TAPS];
            float m = 0.f;
#pragma unroll
            for (int n = 0; n < TAPS; n++) {
                float s = 0.f;
#pragma unroll
                for (int gg = 0; gg < 8; gg++) s += red[(gg * TAPS + n) * 32 + tid];
                a[n] = s + __ldg(bs + n);
                m += a[n];
            }
            m *= (1.f / 9.f);
            float ss = 0.f;
#pragma unroll
            for (int n = 0; n < TAPS; n++) { float d = a[n] - m; ss = fmaf(d, d, ss); }
            float inv = GAIN_OVER_K / (sqrtf(ss * (1.f / 8.f)) + 1e-10f);
            const int pix2 = bx * 32 + tid;
#pragma unroll
            for (int n = 0; n < TAPS; n++)
                g_sf[((size_t)b * TAPS + n) * HW + pix2] = (a[n] - m) * inv;
            __threadfence();
        }
        __syncthreads();
        if (tid == 0) atomicAdd(&g_sfcnt[b], 1u);
        return;
    }

    if (bid < CF_END) {
        // ===================== pool + cf block (w2 staged in 2 halves) ======
        const int t  = bid - SF_END;
        const int b  = t / NCF;
        const int cg = t % NCF;

        float* pooled_s = (float*)sm;                  // 1024 B
        float* y1_s     = (float*)(sm + 1024);         // 256 B
        float* w2c      = (float*)(sm + 1280);         // 72*51*4 = 14688 B
        float* y2_s     = (float*)(sm + 1280 + 14688); // 576 B

#pragma unroll
        for (int h = 0; h < 2; h++) {
            const int c = cg * 16 + w + h * 8;
            const float4* p4 = (const float4*)(x + ((size_t)b * CC + c) * HW);
            float s = 0.f;
            for (int j = lane; j < 784; j += 32) {
                float4 v = __ldg(p4 + j);
                s += (v.x + v.y) + (v.z + v.w);
            }
#pragma unroll
            for (int o = 16; o > 0; o >>= 1) s += __shfl_xor_sync(0xffffffffu, s, o);
            if (lane == 0) g_pooled[b * CC + c] = s * (1.f / (float)HW);
        }
        if (lane == 0) __threadfence();
        __syncthreads();

        if (tid == 0) {
            unsigned v = atomicAdd(&g_pcnt[b], 1u) + 1u;
            u0_s = ((v + 15u) >> 4) << 4;
        }
        // stage w2 half 0 (independent of pooled; overlaps the spin)
        {
            const float4* src = (const float4*)(w2 + (size_t)cg * 144 * MID);
#pragma unroll
            for (int i = tid; i < 72 * MID / 4; i += 256)
                ((float4*)w2c)[i] = __ldg(src + i);
        }
        __syncthreads();
        if (tid == 0) {
            unsigned tgt = u0_s;
            while (*((volatile unsigned*)&g_pcnt[b]) < tgt) __nanosleep(64);
            __threadfence();
        }
        __syncthreads();

        if (tid < CC) pooled_s[tid] = g_pooled[b * CC + tid];
        __syncthreads();

        for (int j = w; j < MID; j += 8) {
            const float* wr = w1 + j * CC;
            float s = 0.f;
#pragma unroll
            for (int k = 0; k < CC / 32; k++)
                s = fmaf(pooled_s[lane + k * 32], __ldg(wr + lane + k * 32), s);
#pragma unroll
            for (int o = 16; o > 0; o >>= 1) s += __shfl_xor_sync(0xffffffffu, s, o);
            if (lane == 0) y1_s[j] = fmaxf(s + __ldg(b1 + j), 0.f);
        }
        __syncthreads();

        // half 0 rows
        if (tid < 72) {
            const int r = cg * 144 + tid;
            float a = __ldg(b2 + r);
            const float* row = w2c + tid * MID;
#pragma unroll
            for (int m = 0; m < MID; m++) a = fmaf(y1_s[m], row[m], a);
            y2_s[tid] = a;
        }
        __syncthreads();
        // stage + compute half 1
        {
            const float4* src = (const float4*)(w2 + ((size_t)cg * 144 + 72) * MID);
#pragma unroll
            for (int i = tid; i < 72 * MID / 4; i += 256)
                ((float4*)w2c)[i] = __ldg(src + i);
        }
        __syncthreads();
        if (tid < 72) {
            const int r = cg * 144 + 72 + tid;
            float a = __ldg(b2 + r);
            const float* row = w2c + tid * MID;
#pragma unroll
            for (int m = 0; m < MID; m++) a = fmaf(y1_s[m], row[m], a);
            y2_s[72 + tid] = a;
        }
        __syncthreads();

        if (tid < 16) {
            const int c = cg * 16 + tid;
            float y[TAPS];
            float m = 0.f;
#pragma unroll
            for (int k = 0; k < TAPS; k++) { y[k] = y2_s[tid * TAPS + k]; m += y[k]; }
            m *= (1.f / 9.f);
            float ss = 0.f;
#pragma unroll
            for (int k = 0; k < TAPS; k++) { float d = y[k] - m; ss = fmaf(d, d, ss); }
            float inv = 1.f / (sqrtf(ss * (1.f / 8.f)) + 1e-10f);
#pragma unroll
            for (int k = 0; k < TAPS; k++)
                g_cf[(size_t)b * CKK + c * TAPS + k] =
                    (y[k] - m) * inv * __ldg(fn_std + c * TAPS + k);
            __threadfence();
        }
        __syncthreads();
        if (tid == 0) atomicAdd(&g_cfcnt[b], 1u);
        return;
    }

    // ===================== ddf block (CG8) =====================
    {
        const int t   = bid - CF_END;
        const int b   = t / NDF;
        const int rem = t % NDF;
        const int cg  = rem / 7;              // 0..31
        const int bx  = rem % 7;
        const int r0  = bx * 8;
        const int c0  = cg * K3_CG;           // channel base

        float* const xh = (float*)(sm) + 4;           // front pad
        ull* cf2_s = (ull*)(sm + 17952);              // 576 B, 16B aligned

        const int tx = tid % 28;
        const int ty = tid / 28;
        const bool act = (tid < 224);
        const int row = r0 + (act ? ty : 0);
        const int col = 2 * tx;

        const unsigned mb = smem_u32(&mbar_st);
        const bool top = (bx == 0), bot = (bx == 6);
        const int nrows = 10 - (top ? 1 : 0) - (bot ? 1 : 0);
        const unsigned tx_bytes = (unsigned)(K3_CG * nrows * WW * 4);

        if (tid == 0) {
            asm volatile("mbarrier.init.shared.b64 [%0], 1;" :: "r"(mb) : "memory");
            unsigned v = atomicAdd(&g_ddftkt[b], 1u);
            unsigned R = v / (unsigned)NDF;
            u0_s = (R + 1u) * (unsigned)NSF;
            u1_s = (R + 1u) * (unsigned)NCF;
        }
        __syncthreads();
        if (tid == 0)
            asm volatile("mbarrier.arrive.expect_tx.shared.b64 _, [%0], %1;"
                         :: "r"(mb), "r"(tx_bytes) : "memory");
        __syncthreads();

        // x bulk copies: input-only, overlap the spins below
        if (tid < K3_CG) {
            const int gr0    = top ? 0 : (r0 - 1);
            const int dst_rr = top ? 1 : 0;
            const float* src = x + ((size_t)(b * CC + c0 + tid) * HW + gr0 * WW);
            const unsigned dst = smem_u32(xh + tid * HSZ + dst_rr * HSTR);
            asm volatile(
                "cp.async.bulk.shared::cta.global.mbarrier::complete_tx::bytes "
                "[%0], [%1], %2, [%3];"
                :: "r"(dst), "l"(src), "r"((unsigned)(nrows * WW * 4)), "r"(mb)
                : "memory");
        }

        if (top || bot) {
            const int zr = top ? 0 : 9;
            for (int i = tid; i < K3_CG * WW; i += 256) {
                int g = i / WW, j = i - g * WW;
                xh[g * HSZ + zr * HSTR + j] = 0.f;
            }
        }

        // spin 1: sf published -> issue sfr loads -> spin 2: cf published
        if (tid == 0) {
            unsigned t0 = u0_s;
            while (*((volatile unsigned*)&g_sfcnt[b]) < t0) __nanosleep(128);
            __threadfence();
        }
        __syncthreads();

        ull sfr[TAPS];
        if (act) {
            const float* sp = g_sf + (size_t)b * TAPS * HW + row * WW + col;
#pragma unroll
            for (int n = 0; n < TAPS; n++)
                sfr[n] = __ldg((const ull*)(sp + n * HW));
        }

        if (tid == 0) {
            unsigned t1 = u1_s;
            while (*((volatile unsigned*)&g_cfcnt[b]) < t1) __nanosleep(128);
            __threadfence();
        }
        __syncthreads();

        if (tid < K3_CG * TAPS) {
            float v = g_cf[(size_t)b * CKK + (size_t)c0 * TAPS + tid];
            cf2_s[tid] = pack2(v, v);
        }
        __syncthreads();   // cf2_s + edge zeros visible

        {
            unsigned done;
            asm volatile(
                "{\n\t.reg .pred p;\n\t"
                "mbarrier.try_wait.parity.acquire.cta.shared::cta.b64 p, [%1], 0;\n\t"
                "selp.b32 %0, 1, 0, p;\n\t}"
                : "=r"(done) : "r"(mb) : "memory");
            if (!done) {
                asm volatile(
                    "{\n\t.reg .pred P1;\n\t"
                    "WL_%=:\n\t"
                    "mbarrier.try_wait.parity.acquire.cta.shared::cta.b64 P1, [%0], 0, 0x989680;\n\t"
                    "@P1 bra.uni WD_%=;\n\t"
                    "bra.uni WL_%=;\n\t"
                    "WD_%=:\n\t}"
                    :: "r"(mb) : "memory");
            }
        }

        if (!act) return;

        const bool eL = (tx == 0);
        const bool eR = (tx == 27);
        const float* hbase = xh + ty * HSTR + col;
        float* po = out + ((size_t)b * CC + c0) * HW + row * WW + col;

#pragma unroll
        for (int g = 0; g < K3_CG; g++) {
            const float* hp = hbase + g * HSZ;
            const ull* cfp = cf2_s + g * TAPS;
            ull acc_u[KK];

#pragma unroll
            for (int u = 0; u < KK; u++) {
                const float* rp = hp + u * HSTR;
                ull A  = *(const ull*)(rp - 2);
                ull Bv = *(const ull*)(rp);
                ull Cv = *(const ull*)(rp + 2);
                float al, ah, bl, bh, cl, ch;
                unpack2(A, al, ah);
                unpack2(Bv, bl, bh);
                unpack2(Cv, cl, ch);
                float xl = eL ? 0.f : ah;
                float xr = eR ? 0.f : cl;
                ull XL = pack2(xl, bl);
                ull XR = pack2(bh, xr);
                ull a = mul2(XL, mul2(cfp[u * 3 + 0], sfr[u * 3 + 0]));
                a = fma2(Bv, mul2(cfp[u * 3 + 1], sfr[u * 3 + 1]), a);
                a = fma2(XR, mul2(cfp[u * 3 + 2], sfr[u * 3 + 2]), a);
                acc_u[u] = a;
            }

            ull acc = add2(add2(acc_u[0], acc_u[1]), acc_u[2]);
            *(ull*)po = acc;
            po += HW;
        }
    }
}

// ---------------------------------------------------------------------------
extern "C" void kernel_launch(void* const* d_in, const int* in_sizes, int n_in,
                              void* d_out, int out_size)
{
    const float* x      = (const float*)d_in[0];
    const float* w1     = (const float*)d_in[1];
    const float* b1     = (const float*)d_in[2];
    const float* w2     = (const float*)d_in[3];
    const float* b2     = (const float*)d_in[4];
    const float* ws     = (const float*)d_in[5];
    const float* bs     = (const float*)d_in[6];
    const float* fn_std = (const float*)d_in[7];
    float* out = (float*)d_out;

    mega<<<CF_END + BB * NDF, 256>>>(x, ws, bs, w1, b1, w2, b2, fn_std, out);
}